// round 8
// baseline (speedup 1.0000x reference)
#include <cuda_runtime.h>
#include <cuda_fp16.h>
#include <cstdint>
#include <cstddef>

#define BB   2048
#define TT   128
#define FF   64
#define HH   256
#define G3   768
#define OL   32
#define FCH  256
#define BM   16
#define ASP  10          // float2 pairs per As row (8 used + 2 pad -> 80B rows, 16B aligned)

// ---- device scratch ----
__device__ __half g_hsh[(size_t)TT * BB * HH];          // [t][b][j] fp16 (ctx source)
__device__ float4 g_W6a[160 * 256];                     // enc packed weights (2k per q)
__device__ float2 g_W6b[160 * 256];
__device__ float4 g_D6a[128 * 256];                     // dec_Whh packed
__device__ float2 g_D6b[128 * 256];
__device__ float2 g_F2 [128 * 256];                     // fc1 packed
__device__ float  g_brz[512], g_bin[256], g_bhn[256];
__device__ float  g_dbrz[512], g_dbin[256], g_dbhn[256];
__device__ float  g_Abt[(size_t)BB * TT];
__device__ float  g_Cbt[(size_t)BB * TT];
__device__ float  g_prev[BB];

typedef unsigned long long u64;

__device__ __forceinline__ void fma2(u64 &d, u64 a, u64 b) {
    asm("fma.rn.f32x2 %0, %1, %2, %0;" : "+l"(d) : "l"(a), "l"(b));
}
__device__ __forceinline__ u64 pack2(float w) {
    u64 r; unsigned int u = __float_as_uint(w);
    asm("mov.b64 %0, {%1,%1};" : "=l"(r) : "r"(u));
    return r;
}
__device__ __forceinline__ float2 u2f(u64 v) {
    float2 r;
    asm("mov.b64 {%0, %1}, %2;" : "=f"(r.x), "=f"(r.y) : "l"(v));
    return r;
}
// two fp16 (packed in u32) -> packed f32x2 (exact widening)
__device__ __forceinline__ u64 hfp(unsigned v) {
    __half2 h2 = *reinterpret_cast<__half2*>(&v);
    float2 f = __half22float2(h2);
    u64 r;
    asm("mov.b64 %0, {%1,%2};" : "=l"(r) : "f"(f.x), "f"(f.y));
    return r;
}
__device__ __forceinline__ float sigf(float x) { return 1.f / (1.f + __expf(-x)); }

// ---- prep: packed weight streams + bias folding + prev0 ----
__global__ void prep_kernel(const float* __restrict__ x,
                            const float* __restrict__ eWih, const float* __restrict__ eWhh,
                            const float* __restrict__ ebih, const float* __restrict__ ebhh,
                            const float* __restrict__ dWhh,
                            const float* __restrict__ dbih, const float* __restrict__ dbhh,
                            const float* __restrict__ fc1W) {
    const int stride = gridDim.x * blockDim.x;
    const int id = blockIdx.x * blockDim.x + threadIdx.x;
    for (int i = id; i < 160 * 256; i += stride) {
        int q = i >> 8, j = i & 255;
        float wr0, wz0, w30, wr1, wz1, w31;
        if (q < 32) {
            int k0 = 2 * q, k1 = k0 + 1;
            wr0 = eWih[j * 64 + k0];         wr1 = eWih[j * 64 + k1];
            wz0 = eWih[(256 + j) * 64 + k0]; wz1 = eWih[(256 + j) * 64 + k1];
            w30 = eWih[(512 + j) * 64 + k0]; w31 = eWih[(512 + j) * 64 + k1];
        } else {
            int k0 = 2 * q - 64, k1 = k0 + 1;
            wr0 = eWhh[j * 256 + k0];         wr1 = eWhh[j * 256 + k1];
            wz0 = eWhh[(256 + j) * 256 + k0]; wz1 = eWhh[(256 + j) * 256 + k1];
            w30 = eWhh[(512 + j) * 256 + k0]; w31 = eWhh[(512 + j) * 256 + k1];
        }
        g_W6a[i] = make_float4(wr0, wz0, w30, wr1);
        g_W6b[i] = make_float2(wz1, w31);
    }
    for (int i = id; i < 128 * 256; i += stride) {
        int q = i >> 8, j = i & 255;
        int k0 = 2 * q, k1 = k0 + 1;
        g_D6a[i] = make_float4(dWhh[j * 256 + k0], dWhh[(256 + j) * 256 + k0],
                               dWhh[(512 + j) * 256 + k0], dWhh[j * 256 + k1]);
        g_D6b[i] = make_float2(dWhh[(256 + j) * 256 + k1], dWhh[(512 + j) * 256 + k1]);
        g_F2[i]  = make_float2(fc1W[j * 256 + k0], fc1W[j * 256 + k1]);
    }
    for (int i = id; i < 512; i += stride) {
        g_brz[i]  = ebih[i] + ebhh[i];
        g_dbrz[i] = dbih[i] + dbhh[i];
    }
    for (int i = id; i < 256; i += stride) {
        g_bin[i]  = ebih[512 + i];  g_bhn[i]  = ebhh[512 + i];
        g_dbin[i] = dbih[512 + i];  g_dbhn[i] = dbhh[512 + i];
    }
    for (int i = id; i < BB; i += stride)
        g_prev[i] = x[((size_t)i * TT + (TT - 1)) * FF];
}

// position i (0..159 within step, cyclic) -> weight index q
__device__ __forceinline__ int sidx(int i, int offx, int offh) {
    if (i >= 160) i -= 160;
    return (i < 32) ? ((offx + i) & 31) : (32 + ((offh + (i - 32)) & 127));
}

// 2-k FMA body with named weight regs
#define ENC_BODY(Q, WA, WB, AS) do {                                                       \
    const double2* _av0 = reinterpret_cast<const double2*>(As + (2 * (Q)) * ASP);          \
    const double2* _av1 = reinterpret_cast<const double2*>(As + (2 * (Q) + 1) * ASP);      \
    u64 _p00 = pack2(WA.x), _p01 = pack2(WA.y), _p02 = pack2(WA.z);                        \
    u64 _p10 = pack2(WA.w), _p11 = pack2(WB.x), _p12 = pack2(WB.y);                        \
    _Pragma("unroll")                                                                      \
    for (int _h = 0; _h < 4; _h++) {                                                       \
        double2 _d0 = _av0[_h], _d1 = _av1[_h];                                            \
        u64 _a00 = __double_as_longlong(_d0.x), _a01 = __double_as_longlong(_d0.y);        \
        u64 _a10 = __double_as_longlong(_d1.x), _a11 = __double_as_longlong(_d1.y);        \
        fma2(aR[2*_h],   _p00, _a00); fma2(aZ[2*_h],   _p01, _a00); fma2(AS[2*_h],   _p02, _a00); \
        fma2(aR[2*_h+1], _p00, _a01); fma2(aZ[2*_h+1], _p01, _a01); fma2(AS[2*_h+1], _p02, _a01); \
        fma2(aR[2*_h],   _p10, _a10); fma2(aZ[2*_h],   _p11, _a10); fma2(AS[2*_h],   _p12, _a10); \
        fma2(aR[2*_h+1], _p10, _a11); fma2(aZ[2*_h+1], _p11, _a11); fma2(AS[2*_h+1], _p12, _a11); \
    }                                                                                      \
} while (0)

// ---- persistent encoder: all 128 steps, h in smem, gates in registers,
//      prefetch-depth-2 weight pipeline, exact A/C in-kernel ----
__global__ void __launch_bounds__(256, 1) enc_all_kernel(const float* __restrict__ x,
                                                         const float* __restrict__ h0,
                                                         const float* __restrict__ wq,
                                                         const float* __restrict__ bq) {
    __shared__ float2 As[320 * ASP];            // x rows 0..63, h rows 64..319
    __shared__ float2 redA[8 * 8], redC[8 * 8]; // [warp][pair]
    float* Asf = reinterpret_cast<float*>(As);
    const int tid = threadIdx.x;
    const int B0 = blockIdx.x * BM;
    const int wid = tid >> 5, lane = tid & 31;

    for (int i = tid; i < BM * HH; i += 256) {
        int b = i >> 8, k = i & 255;
        Asf[((64 + k) * ASP + (b >> 1)) * 2 + (b & 1)] = h0[(size_t)(B0 + b) * HH + k];
    }
    for (int i = tid; i < BM * FF; i += 256) {
        int b = i >> 6, k = i & 63;
        Asf[(k * ASP + (b >> 1)) * 2 + (b & 1)] = x[((size_t)(B0 + b) * TT + 0) * FF + k];
    }
    const float brz1 = g_brz[tid], brz2 = g_brz[256 + tid];
    const float bi = g_bin[tid], bh = g_bhn[tid];
    const float wqj = wq[tid], bqj = bq[tid];
    const int offx = blockIdx.x & 31;
    const int offh = (blockIdx.x * 37) & 127;
    __syncthreads();

    // steady-state 2-deep weight pipeline (A = pos i, B = pos i+1)
    int qA = sidx(0, offx, offh), qB = sidx(1, offx, offh);
    float4 waA = g_W6a[qA * 256 + tid]; float2 wbA = g_W6b[qA * 256 + tid];
    float4 waB = g_W6a[qB * 256 + tid]; float2 wbB = g_W6b[qB * 256 + tid];

    for (int t = 0; t < TT; t++) {
        // prefetch x_{t+1}
        float xr[4];
#pragma unroll
        for (int r = 0; r < 4; r++) {
            int i = tid + 256 * r;
            int b = i >> 6, k = i & 63;
            xr[r] = (t + 1 < TT) ? x[((size_t)(B0 + b) * TT + (t + 1)) * FF + k] : 0.f;
        }

        u64 aR[8], aZ[8], aI[8], aH[8];
#pragma unroll
        for (int p = 0; p < 8; p++) { aR[p] = 0; aZ[p] = 0; aI[p] = 0; aH[p] = 0; }

        for (int i = 0; i < 32; i += 2) {            // x-part (k<64): r,z,i_n
            int qC = sidx(i + 2, offx, offh);
            float4 waC = g_W6a[qC * 256 + tid]; float2 wbC = g_W6b[qC * 256 + tid];
            ENC_BODY(qA, waA, wbA, aI);
            int qD = sidx(i + 3, offx, offh);
            float4 waD = g_W6a[qD * 256 + tid]; float2 wbD = g_W6b[qD * 256 + tid];
            ENC_BODY(qB, waB, wbB, aI);
            qA = qC; waA = waC; wbA = wbC;
            qB = qD; waB = waD; wbB = wbD;
        }
        for (int i = 32; i < 160; i += 2) {          // h-part (k>=64): r,z,h_n
            int qC = sidx(i + 2, offx, offh);
            float4 waC = g_W6a[qC * 256 + tid]; float2 wbC = g_W6b[qC * 256 + tid];
            ENC_BODY(qA, waA, wbA, aH);
            int qD = sidx(i + 3, offx, offh);
            float4 waD = g_W6a[qD * 256 + tid]; float2 wbD = g_W6b[qD * 256 + tid];
            ENC_BODY(qB, waB, wbB, aH);
            qA = qC; waA = waC; wbA = wbC;
            qB = qD; waB = waD; wbB = wbD;
        }
        __syncthreads();   // all GEMM reads of As done

        // GRU elementwise in-register; h update in smem; fp16 hs store; A/C partials
        __half* __restrict__ hsh = g_hsh + ((size_t)t * BB + B0) * HH + tid;
#pragma unroll
        for (int p = 0; p < 8; p++) {
            float2 fr = u2f(aR[p]), fz = u2f(aZ[p]), fi = u2f(aI[p]), fh = u2f(aH[p]);
            float2 hp = As[(64 + tid) * ASP + p];
            float r0 = sigf(fr.x + brz1), z0 = sigf(fz.x + brz2);
            float n0 = tanhf(fi.x + bi + r0 * (fh.x + bh));
            float h0n = (1.f - z0) * n0 + z0 * hp.x;
            float r1 = sigf(fr.y + brz1), z1 = sigf(fz.y + brz2);
            float n1 = tanhf(fi.y + bi + r1 * (fh.y + bh));
            float h1n = (1.f - z1) * n1 + z1 * hp.y;
            As[(64 + tid) * ASP + p] = make_float2(h0n, h1n);
            hsh[(size_t)(2 * p) * HH]     = __float2half_rn(h0n);
            hsh[(size_t)(2 * p + 1) * HH] = __float2half_rn(h1n);
            float2 pa = make_float2(wqj * h0n, wqj * h1n);
            float2 pc = make_float2(bqj * h0n, bqj * h1n);
#pragma unroll
            for (int o = 16; o > 0; o >>= 1) {
                pa.x += __shfl_xor_sync(0xffffffffu, pa.x, o);
                pa.y += __shfl_xor_sync(0xffffffffu, pa.y, o);
                pc.x += __shfl_xor_sync(0xffffffffu, pc.x, o);
                pc.y += __shfl_xor_sync(0xffffffffu, pc.y, o);
            }
            if (lane == 0) { redA[wid * 8 + p] = pa; redC[wid * 8 + p] = pc; }
        }
        // store x_{t+1}
#pragma unroll
        for (int r = 0; r < 4; r++) {
            int i = tid + 256 * r;
            int b = i >> 6, k = i & 63;
            Asf[(k * ASP + (b >> 1)) * 2 + (b & 1)] = xr[r];
        }
        __syncthreads();   // As + redA/redC ready

        if (tid < 8) {     // finalize A/C for this block's 16 batches
            float2 A = make_float2(0.f, 0.f), C = make_float2(0.f, 0.f);
#pragma unroll
            for (int w = 0; w < 8; w++) {
                float2 a = redA[w * 8 + tid], c = redC[w * 8 + tid];
                A.x += a.x; A.y += a.y; C.x += c.x; C.y += c.y;
            }
            g_Abt[(size_t)(B0 + 2 * tid) * TT + t]     = A.x * 0.0625f;
            g_Abt[(size_t)(B0 + 2 * tid + 1) * TT + t] = A.y * 0.0625f;
            g_Cbt[(size_t)(B0 + 2 * tid) * TT + t]     = C.x * 0.0625f;
            g_Cbt[(size_t)(B0 + 2 * tid + 1) * TT + t] = C.y * 0.0625f;
        }
    }
}

#define DEC_BODY(Q, WA, WB) do {                                                           \
    const double2* _av0 = reinterpret_cast<const double2*>(ctxp + (2 * (Q)) * 8);          \
    const double2* _av1 = reinterpret_cast<const double2*>(ctxp + (2 * (Q) + 1) * 8);      \
    u64 _p00 = pack2(WA.x), _p01 = pack2(WA.y), _p02 = pack2(WA.z);                        \
    u64 _p10 = pack2(WA.w), _p11 = pack2(WB.x), _p12 = pack2(WB.y);                        \
    _Pragma("unroll")                                                                      \
    for (int _h = 0; _h < 4; _h++) {                                                       \
        double2 _d0 = _av0[_h], _d1 = _av1[_h];                                            \
        u64 _a00 = __double_as_longlong(_d0.x), _a01 = __double_as_longlong(_d0.y);        \
        u64 _a10 = __double_as_longlong(_d1.x), _a11 = __double_as_longlong(_d1.y);        \
        fma2(ar[2*_h],   _p00, _a00); fma2(az[2*_h],   _p01, _a00); fma2(an[2*_h],   _p02, _a00); \
        fma2(ar[2*_h+1], _p00, _a01); fma2(az[2*_h+1], _p01, _a01); fma2(an[2*_h+1], _p02, _a01); \
        fma2(ar[2*_h],   _p10, _a10); fma2(az[2*_h],   _p11, _a10); fma2(an[2*_h],   _p12, _a10); \
        fma2(ar[2*_h+1], _p10, _a11); fma2(az[2*_h+1], _p11, _a11); fma2(an[2*_h+1], _p12, _a11); \
    }                                                                                      \
} while (0)

// ---- persistent decoder: all 32 steps fused ----
__global__ void __launch_bounds__(256, 1) dec_all_kernel(const float* __restrict__ dWih,
                                                         const float* __restrict__ fc1b,
                                                         const float* __restrict__ fc2W,
                                                         const float* __restrict__ fc2b,
                                                         float* __restrict__ out) {
    __shared__ char smraw[8192 + 16384 + 16384 + 64];
    float*  s     = reinterpret_cast<float*>(smraw);                 // [16][128]
    float2* ctxp  = reinterpret_cast<float2*>(smraw + 8192);         // [256][8] pairs
    float*  f1s   = reinterpret_cast<float*>(smraw + 8192);          // overlays ctxp
    float2* hdp   = reinterpret_cast<float2*>(smraw + 8192 + 16384); // [256][8] pairs
    float*  prevs = reinterpret_cast<float*>(smraw + 8192 + 32768);  // [16]
    const int tid = threadIdx.x;
    const int B0 = blockIdx.x * BM;
    const int wid = tid >> 5, lane = tid & 31;
    const int j = tid;
    const int toff = (blockIdx.x * 29) & 127;
    const int qoff = (blockIdx.x * 13) & 127;

    if (tid < BM) prevs[tid] = g_prev[B0 + tid];
    const float dwr = dWih[j], dwz = dWih[256 + j], dwn = dWih[512 + j];
    const float br = g_dbrz[j], bz = g_dbrz[256 + j], bi = g_dbin[j], bh = g_dbhn[j];
    const float b1 = fc1b[tid], fb = fc2b[0];
    float w2r[8];
#pragma unroll
    for (int qq = 0; qq < 8; qq++) w2r[qq] = fc2W[lane + 32 * qq];
    __syncthreads();

    for (int step = 0; step < OL; step++) {
        for (int i = tid; i < BM * TT; i += 256) {
            int b = i >> 7;
            s[i] = prevs[b] * g_Abt[(size_t)B0 * TT + i] + g_Cbt[(size_t)B0 * TT + i];
        }
        __syncthreads();

#pragma unroll
        for (int bb = 0; bb < 2; bb++) {
            int b = wid * 2 + bb;
            float v0 = s[b*TT+lane], v1 = s[b*TT+lane+32], v2 = s[b*TT+lane+64], v3 = s[b*TT+lane+96];
            float m = fmaxf(fmaxf(v0, v1), fmaxf(v2, v3));
#pragma unroll
            for (int o = 16; o > 0; o >>= 1) m = fmaxf(m, __shfl_xor_sync(0xffffffffu, m, o));
            float e0 = __expf(v0-m), e1 = __expf(v1-m), e2 = __expf(v2-m), e3 = __expf(v3-m);
            float sum = e0 + e1 + e2 + e3;
#pragma unroll
            for (int o = 16; o > 0; o >>= 1) sum += __shfl_xor_sync(0xffffffffu, sum, o);
            float inv = 1.f / sum;
            s[b*TT+lane] = e0*inv; s[b*TT+lane+32] = e1*inv; s[b*TT+lane+64] = e2*inv; s[b*TT+lane+96] = e3*inv;
        }
        __syncthreads();

        {   // ctx[b][j] = sum_t w[b,t] * hs_fp16[t][b][j], fp32 packed accumulate
            const int jv = (tid & 63) * 4;
            const int bs = tid >> 6;
            u64 c0[2] = {0,0}, c1[2] = {0,0}, c2[2] = {0,0}, c3[2] = {0,0};
#pragma unroll 4
            for (int i = 0; i < TT; i++) {
                int t = (i + toff) & 127;
                const uint2* hb = reinterpret_cast<const uint2*>(
                    g_hsh + ((size_t)t * BB + B0) * HH) + (jv >> 2);
                float w0 = s[(bs+0)*TT+t], w1 = s[(bs+4)*TT+t], w2 = s[(bs+8)*TT+t], w3 = s[(bs+12)*TT+t];
                uint2 v0 = hb[(bs+0)*64], v1 = hb[(bs+4)*64], v2 = hb[(bs+8)*64], v3 = hb[(bs+12)*64];
                u64 wp0 = pack2(w0), wp1 = pack2(w1), wp2 = pack2(w2), wp3 = pack2(w3);
                fma2(c0[0], wp0, hfp(v0.x)); fma2(c0[1], wp0, hfp(v0.y));
                fma2(c1[0], wp1, hfp(v1.x)); fma2(c1[1], wp1, hfp(v1.y));
                fma2(c2[0], wp2, hfp(v2.x)); fma2(c2[1], wp2, hfp(v2.y));
                fma2(c3[0], wp3, hfp(v3.x)); fma2(c3[1], wp3, hfp(v3.y));
            }
            float* cf = reinterpret_cast<float*>(ctxp);
            u64* cc[4] = {c0, c1, c2, c3};
#pragma unroll
            for (int qq = 0; qq < 4; qq++) {
                int b = bs + 4 * qq, p = b >> 1, par = b & 1;
                float2 lo = u2f(cc[qq][0]), hi = u2f(cc[qq][1]);
                cf[((jv+0)*8+p)*2+par] = lo.x; cf[((jv+1)*8+p)*2+par] = lo.y;
                cf[((jv+2)*8+p)*2+par] = hi.x; cf[((jv+3)*8+p)*2+par] = hi.y;
            }
        }
        __syncthreads();

        u64 ar[8], az[8], an[8];
#pragma unroll
        for (int p = 0; p < 8; p++) { ar[p] = 0; az[p] = 0; an[p] = 0; }
        {   // gh = ctx @ dec_Whh^T (staggered, prefetch depth 2)
            int qA = qoff, qB = (qoff + 1) & 127;
            float4 waA = g_D6a[qA * 256 + tid]; float2 wbA = g_D6b[qA * 256 + tid];
            float4 waB = g_D6a[qB * 256 + tid]; float2 wbB = g_D6b[qB * 256 + tid];
            for (int i = 0; i < 128; i += 2) {
                int qC = (qoff + i + 2) & 127;
                float4 waC = g_D6a[qC * 256 + tid]; float2 wbC = g_D6b[qC * 256 + tid];
                DEC_BODY(qA, waA, wbA);
                int qD = (qoff + i + 3) & 127;
                float4 waD = g_D6a[qD * 256 + tid]; float2 wbD = g_D6b[qD * 256 + tid];
                DEC_BODY(qB, waB, wbB);
                qA = qC; waA = waC; wbA = wbC;
                qB = qD; waB = waD; wbB = wbD;
            }
        }
        {   // decoder GRU elementwise (x = prev scalar, h = ctx)
#pragma unroll
            for (int p = 0; p < 8; p++) {
                float2 fr = u2f(ar[p]), fz = u2f(az[p]), fn = u2f(an[p]);
                float2 cx = ctxp[j * 8 + p];
                float2 hd;
                float pv = prevs[2 * p];
                float r = sigf(pv * dwr + fr.x + br);
                float z = sigf(pv * dwz + fz.x + bz);
                float n = tanhf(pv * dwn + bi + r * (fn.x + bh));
                hd.x = (1.f - z) * n + z * cx.x;
                pv = prevs[2 * p + 1];
                r = sigf(pv * dwr + fr.y + br);
                z = sigf(pv * dwz + fz.y + bz);
                n = tanhf(pv * dwn + bi + r * (fn.y + bh));
                hd.y = (1.f - z) * n + z * cx.y;
                hdp[j * 8 + p] = hd;
            }
        }
        __syncthreads();   // hdp ready; ctxp reusable as f1s

        {   // fc1 + relu (staggered, prefetch depth 2)
            u64 f[8];
#pragma unroll
            for (int p = 0; p < 8; p++) f[p] = 0;
            int qA = qoff, qB = (qoff + 1) & 127;
            float2 wfA = g_F2[qA * 256 + tid];
            float2 wfB = g_F2[qB * 256 + tid];
#define FC1_BODY(Q, WF) do {                                                         \
                const double2* hv0 = reinterpret_cast<const double2*>(hdp + (2 * (Q)) * 8);     \
                const double2* hv1 = reinterpret_cast<const double2*>(hdp + (2 * (Q) + 1) * 8); \
                u64 w0 = pack2(WF.x), w1 = pack2(WF.y);                              \
                _Pragma("unroll")                                                    \
                for (int h = 0; h < 4; h++) {                                        \
                    double2 d0 = hv0[h], d1 = hv1[h];                                \
                    fma2(f[2*h],   w0, __double_as_longlong(d0.x));                  \
                    fma2(f[2*h+1], w0, __double_as_longlong(d0.y));                  \
                    fma2(f[2*h],   w1, __double_as_longlong(d1.x));                  \
                    fma2(f[2*h+1], w1, __double_as_longlong(d1.y));                  \
                }                                                                    \
            } while (0)
            for (int i = 0; i < 128; i += 2) {
                int qC = (qoff + i + 2) & 127;
                float2 wfC = g_F2[qC * 256 + tid];
                FC1_BODY(qA, wfA);
                int qD = (qoff + i + 3) & 127;
                float2 wfD = g_F2[qD * 256 + tid];
                FC1_BODY(qB, wfB);
                qA = qC; wfA = wfC;
                qB = qD; wfB = wfD;
            }
#undef FC1_BODY
#pragma unroll
            for (int p = 0; p < 8; p++) {
                float2 v = u2f(f[p]);
                f1s[(2*p)*FCH + tid]   = fmaxf(v.x + b1, 0.f);
                f1s[(2*p+1)*FCH + tid] = fmaxf(v.y + b1, 0.f);
            }
        }
        __syncthreads();

        {   // fc2: warp reduces 2 batches; carry prev in smem
#pragma unroll
            for (int bb = 0; bb < 2; bb++) {
                int b = wid * 2 + bb;
                float a = 0.f;
#pragma unroll
                for (int qq = 0; qq < 8; qq++)
                    a += f1s[b * FCH + lane + 32 * qq] * w2r[qq];
#pragma unroll
                for (int o = 16; o > 0; o >>= 1) a += __shfl_xor_sync(0xffffffffu, a, o);
                if (lane == 0) {
                    float v = a + fb;
                    out[(size_t)(B0 + b) * OL + step] = v;
                    prevs[b] = v;
                }
            }
        }
        __syncthreads();
    }
}

extern "C" void kernel_launch(void* const* d_in, const int* in_sizes, int n_in,
                              void* d_out, int out_size) {
    const float* x      = (const float*)d_in[0];
    const float* h      = (const float*)d_in[1];
    const float* eWih   = (const float*)d_in[2];
    const float* eWhh   = (const float*)d_in[3];
    const float* ebih   = (const float*)d_in[4];
    const float* ebhh   = (const float*)d_in[5];
    const float* dWih   = (const float*)d_in[6];
    const float* dWhh   = (const float*)d_in[7];
    const float* dbih   = (const float*)d_in[8];
    const float* dbhh   = (const float*)d_in[9];
    const float* wq     = (const float*)d_in[10];
    const float* bq     = (const float*)d_in[11];
    const float* fc1W   = (const float*)d_in[12];
    const float* fc1b   = (const float*)d_in[13];
    const float* fc2W   = (const float*)d_in[14];
    const float* fc2b   = (const float*)d_in[15];
    float* out = (float*)d_out;

    prep_kernel<<<256, 256>>>(x, eWih, eWhh, ebih, ebhh, dWhh, dbih, dbhh, fc1W);
    enc_all_kernel<<<BB / BM, 256>>>(x, h, wq, bq);
    dec_all_kernel<<<BB / BM, 256>>>(dWih, fc1b, fc2W, fc2b, out);
}